// round 3
// baseline (speedup 1.0000x reference)
#include <cuda_runtime.h>
#include <cstdint>

#define N_NODES 8192
#define F_IN    200
#define F_OUT   100
#define NPAD    128     // padded output-column count for the big GEMM
#define KSPLIT  4
#define RSPLIT  16      // row splits for the column-sum

// ---------------- scratch (no allocations allowed) ----------------
__device__ __align__(16) float g_colsum_part[RSPLIT * N_NODES];
__device__ __align__(16) float g_colsum[N_NODES];
__device__ __align__(16) float g_Wt[F_IN * NPAD];                       // W transposed, [F_IN][NPAD]
__device__ __align__(16) float g_G[(size_t)N_NODES * NPAD];             // diag(dinv) h0 W^T, padded
__device__ __align__(16) float g_P[(size_t)KSPLIT * N_NODES * NPAD];    // split-K partials of A@G

// ---------------- 1) column sums of A (deterministic, no atomics) ----------------
__global__ void colsum_part_kernel(const float* __restrict__ A) {
    int j  = blockIdx.x * 256 + threadIdx.x;
    int i0 = blockIdx.y * (N_NODES / RSPLIT);
    const float* p = A + (size_t)i0 * N_NODES + j;
    float s = 0.f;
    #pragma unroll 8
    for (int i = 0; i < N_NODES / RSPLIT; i++)
        s += p[(size_t)i * N_NODES];
    g_colsum_part[blockIdx.y * N_NODES + j] = s;
}

__global__ void colsum_fin_kernel() {
    int j = blockIdx.x * 256 + threadIdx.x;
    float s = 1.0f;                       // the +I diagonal contribution
    #pragma unroll
    for (int p = 0; p < RSPLIT; p++)
        s += g_colsum_part[p * N_NODES + j];
    g_colsum[j] = s;
}

// ---------------- 2) transpose W so projection reads are coalesced ----------------
__global__ void wt_kernel(const float* __restrict__ W) {
    int idx = blockIdx.x * 256 + threadIdx.x;
    if (idx < F_OUT * F_IN) {
        int o = idx / F_IN, f = idx % F_IN;
        g_Wt[f * NPAD + o] = W[idx];
    }
}

// ---------------- 3) G = diag(dinv) * h0 @ W^T  (padded to NPAD cols) ----------------
__global__ void g_kernel(const float* __restrict__ h0) {
    __shared__ float hrow[F_IN];
    int j = blockIdx.x;
    int t = threadIdx.x;                  // 128 threads
    for (int f = t; f < F_IN; f += 128)
        hrow[f] = h0[(size_t)j * F_IN + f];
    __syncthreads();
    float dj  = rsqrtf(g_colsum[j]);
    float out = 0.f;
    if (t < F_OUT) {
        float s = 0.f;
        #pragma unroll 8
        for (int f = 0; f < F_IN; f++)
            s = fmaf(hrow[f], g_Wt[f * NPAD + t], s);
        out = dj * s;
    }
    g_G[(size_t)j * NPAD + t] = out;      // pad cols [100,128) get exact zeros
}

// ---------------- 4) big GEMM: P[ks] = A[:, kchunk] @ G[kchunk, :]  ----------------
// BM=128, BN=128, KT=32, 256 threads, 8x8 thread tile, packed f32x2 FMA mainloop.
__global__ __launch_bounds__(256, 1) void gemm_kernel(const float* __restrict__ A) {
    __shared__ __align__(16) float As[128][33];   // [row][k], pad 33 kills bank conflicts
    __shared__ __align__(16) float Bs[32][128];   // [k][col]

    const int tid  = threadIdx.x;
    const int row0 = blockIdx.x * 128;
    const int k0   = blockIdx.y * (N_NODES / KSPLIT);   // 2048-wide K chunk

    const int arow = tid >> 3;            // 0..31   (A tile loader)
    const int acol = (tid & 7) << 2;      // 0,4..28
    const int brow = tid >> 5;            // 0..7    (B tile loader)
    const int bcol = (tid & 31) << 2;     // 0..124
    const int ty   = tid >> 4;            // 0..15 -> rows ty*8..ty*8+7
    const int tx   = tid & 15;            // 0..15 -> cols tx*8..tx*8+7

    const float* Abase = A   + (size_t)row0 * N_NODES + k0;
    const float* Gbase = g_G + (size_t)k0 * NPAD;

    float4 abuf[4], bbuf[4];
    #pragma unroll
    for (int p = 0; p < 4; p++)
        abuf[p] = *(const float4*)(Abase + (size_t)(p * 32 + arow) * N_NODES + acol);
    #pragma unroll
    for (int p = 0; p < 4; p++)
        bbuf[p] = *(const float4*)(Gbase + (p * 8 + brow) * NPAD + bcol);

    unsigned long long acc[8][4];         // each holds 2 packed fp32 accumulators
    #pragma unroll
    for (int m = 0; m < 8; m++)
        #pragma unroll
        for (int n = 0; n < 4; n++) acc[m][n] = 0ull;

    const int NT = (N_NODES / KSPLIT) / 32;   // 64 K-tiles
    for (int kt = 0; kt < NT; kt++) {
        // commit prefetched tile to smem
        #pragma unroll
        for (int p = 0; p < 4; p++) {
            int r = p * 32 + arow;
            As[r][acol + 0] = abuf[p].x;  As[r][acol + 1] = abuf[p].y;
            As[r][acol + 2] = abuf[p].z;  As[r][acol + 3] = abuf[p].w;
        }
        #pragma unroll
        for (int p = 0; p < 4; p++)
            *(float4*)&Bs[p * 8 + brow][bcol] = bbuf[p];
        __syncthreads();

        // prefetch next tile into registers while computing this one
        if (kt + 1 < NT) {
            const float* An = Abase + (kt + 1) * 32;
            const float* Gn = Gbase + (size_t)(kt + 1) * 32 * NPAD;
            #pragma unroll
            for (int p = 0; p < 4; p++)
                abuf[p] = *(const float4*)(An + (size_t)(p * 32 + arow) * N_NODES + acol);
            #pragma unroll
            for (int p = 0; p < 4; p++)
                bbuf[p] = *(const float4*)(Gn + (p * 8 + brow) * NPAD + bcol);
        }

        #pragma unroll
        for (int kk = 0; kk < 32; kk++) {
            unsigned long long a2[8], b2[4];
            #pragma unroll
            for (int m = 0; m < 8; m++) {
                unsigned int av = __float_as_uint(As[ty * 8 + m][kk]);
                asm("mov.b64 %0, {%1, %1};" : "=l"(a2[m]) : "r"(av));
            }
            #pragma unroll
            for (int n = 0; n < 4; n++)
                b2[n] = *(const unsigned long long*)&Bs[kk][tx * 8 + n * 2];
            #pragma unroll
            for (int m = 0; m < 8; m++)
                #pragma unroll
                for (int n = 0; n < 4; n++)
                    asm("fma.rn.f32x2 %0, %1, %2, %0;"
                        : "+l"(acc[m][n]) : "l"(a2[m]), "l"(b2[n]));
        }
        __syncthreads();
    }

    float* P = g_P + ((size_t)blockIdx.y * N_NODES + row0) * NPAD;
    #pragma unroll
    for (int m = 0; m < 8; m++)
        #pragma unroll
        for (int n = 0; n < 4; n++)
            *(unsigned long long*)(P + (size_t)(ty * 8 + m) * NPAD + tx * 8 + n * 2) = acc[m][n];
}

// ---------------- 5) epilogue: reduce split-K, add I-term, scale, bias, relu -------
__global__ void epi_kernel(const float* __restrict__ b, float* __restrict__ out) {
    int idx = blockIdx.x * 256 + threadIdx.x;   // over N_NODES * NPAD
    int i = idx >> 7, o = idx & 127;
    if (o < F_OUT) {
        const size_t S = (size_t)N_NODES * NPAD;
        float s = g_P[idx] + g_P[idx + S] + g_P[idx + 2 * S] + g_P[idx + 3 * S]
                + g_G[idx];                           // + I * G  (row i term)
        float v = fmaf(rsqrtf(g_colsum[i]), s, b[o]); // dinv_i * s + b_o
        out[(size_t)i * F_OUT + o] = fmaxf(v, 0.f);
    }
}

// ---------------- launch ----------------
extern "C" void kernel_launch(void* const* d_in, const int* in_sizes, int n_in,
                              void* d_out, int out_size) {
    // identify inputs by element count (robust to metadata ordering)
    const float *A = nullptr, *h0 = nullptr, *W = nullptr, *b = nullptr;
    for (int i = 0; i < n_in; i++) {
        switch (in_sizes[i]) {
            case N_NODES * N_NODES: A  = (const float*)d_in[i]; break;
            case N_NODES * F_IN:    h0 = (const float*)d_in[i]; break;
            case F_OUT * F_IN:      W  = (const float*)d_in[i]; break;
            case F_OUT:             b  = (const float*)d_in[i]; break;
        }
    }
    float* out = (float*)d_out;

    colsum_part_kernel<<<dim3(N_NODES / 256, RSPLIT), 256>>>(A);
    colsum_fin_kernel<<<N_NODES / 256, 256>>>();
    wt_kernel<<<(F_OUT * F_IN + 255) / 256, 256>>>(W);
    g_kernel<<<N_NODES, 128>>>(h0);
    gemm_kernel<<<dim3(N_NODES / 128, KSPLIT), 256>>>(A);
    epi_kernel<<<(N_NODES * NPAD) / 256, 256>>>(b, out);
}

// round 6
// speedup vs baseline: 2.1708x; 2.1708x over previous
#include <cuda_runtime.h>
#include <cstdint>

#define N_NODES 8192
#define F_IN    200
#define F_OUT   100
#define NPAD    128
#define KSPLIT  2
#define RSPLIT  16

// ---------------- scratch (no allocations allowed) ----------------
__device__ __align__(16) float g_colsum_part[RSPLIT * N_NODES];
__device__ __align__(16) float g_colsum[N_NODES];
__device__ __align__(16) float g_Wt[F_IN * NPAD];                       // [F_IN][NPAD]
__device__ __align__(16) float g_G [(size_t)N_NODES * NPAD];            // diag(dinv) h0 W^T (tf32-rounded)
__device__ __align__(16) float g_P [(size_t)KSPLIT * N_NODES * NPAD];   // split-K partials

// ================= helpers =================
__device__ __forceinline__ uint32_t smem_u32(const void* p) {
    uint32_t a;
    asm("{ .reg .u64 t; cvta.to.shared.u64 t, %1; cvt.u32.u64 %0, t; }" : "=r"(a) : "l"(p));
    return a;
}
__device__ __forceinline__ void cp16(uint32_t s, const void* g) {
    asm volatile("cp.async.cg.shared.global [%0], [%1], 16;" :: "r"(s), "l"(g) : "memory");
}
__device__ __forceinline__ uint32_t f2tf32(float x) {   // round-to-nearest tf32 (unbiased)
    uint32_t u;
    asm("cvt.rna.tf32.f32 %0, %1;" : "=r"(u) : "f"(x));
    return u;
}

// ---------------- 1) column sums of A ----------------
__global__ void colsum_part_kernel(const float* __restrict__ A) {
    int j  = blockIdx.x * 256 + threadIdx.x;
    int i0 = blockIdx.y * (N_NODES / RSPLIT);
    const float* p = A + (size_t)i0 * N_NODES + j;
    float s = 0.f;
    #pragma unroll 8
    for (int i = 0; i < N_NODES / RSPLIT; i++) s += p[(size_t)i * N_NODES];
    g_colsum_part[blockIdx.y * N_NODES + j] = s;
}
__global__ void colsum_fin_kernel() {
    int j = blockIdx.x * 256 + threadIdx.x;
    float s = 1.0f;
    #pragma unroll
    for (int p = 0; p < RSPLIT; p++) s += g_colsum_part[p * N_NODES + j];
    g_colsum[j] = s;
}

// ---------------- 2) W -> Wt (zero-padded to NPAD cols) ----------------
__global__ void wt_kernel(const float* __restrict__ W) {
    int idx = blockIdx.x * 256 + threadIdx.x;   // over F_IN*NPAD
    if (idx < F_IN * NPAD) {
        int f = idx >> 7, o = idx & 127;
        g_Wt[idx] = (o < F_OUT) ? W[o * F_IN + f] : 0.f;
    }
}

// ---------------- 3) G = diag(dinv) h0 @ Wt, tf32-rounded on store ----------------
__global__ __launch_bounds__(256) void g_kernel(const float* __restrict__ h0) {
    __shared__ float h0s[32][8];
    __shared__ float Wts[8][128];
    int t  = threadIdx.x;
    int tx = t & 31, ty = t >> 5;          // ty 0..7
    int row0 = blockIdx.x * 32;
    float acc[4][4] = {};

    for (int kc = 0; kc < F_IN; kc += 8) {
        __syncthreads();
        { int r = t >> 3, kk = t & 7;
          h0s[r][kk] = h0[(size_t)(row0 + r) * F_IN + kc + kk]; }
        *(float4*)&Wts[ty][tx * 4] = *(const float4*)&g_Wt[(kc + ty) * NPAD + tx * 4];
        __syncthreads();
        #pragma unroll
        for (int k2 = 0; k2 < 8; k2++) {
            float b[4]; *(float4*)b = *(float4*)&Wts[k2][tx * 4];
            #pragma unroll
            for (int i = 0; i < 4; i++) {
                float a = h0s[ty * 4 + i][k2];
                #pragma unroll
                for (int j = 0; j < 4; j++) acc[i][j] = fmaf(a, b[j], acc[i][j]);
            }
        }
    }
    #pragma unroll
    for (int i = 0; i < 4; i++) {
        int row = row0 + ty * 4 + i;
        float dj = rsqrtf(g_colsum[row]);
        uint4 v;
        v.x = f2tf32(acc[i][0] * dj);  v.y = f2tf32(acc[i][1] * dj);
        v.z = f2tf32(acc[i][2] * dj);  v.w = f2tf32(acc[i][3] * dj);
        *(uint4*)&g_G[(size_t)row * NPAD + tx * 4] = v;
    }
}

// ---------------- 4) tf32 mma.sync GEMM: P[ks] = A[:,kchunk] @ G[kchunk,:] -------
// CTA tile 128x128, KT=32, 3-stage cp.async pipeline, 8 warps, warp tile 64x32.
#define KT        32
#define STAGES    3
#define A_STRIDE  36                       // bank = (4r+c)%32 = lane  -> conflict-free
#define B_STRIDE  136                      // bank = (8k+n)%32         -> conflict-free
#define SMA_BYTES (128 * A_STRIDE * 4)     // 18432
#define SMB_BYTES (KT * B_STRIDE * 4)      // 17408
#define STAGE_BYTES (SMA_BYTES + SMB_BYTES)
#define GEMM_SMEM   (STAGES * STAGE_BYTES) // 107520

__device__ __forceinline__ void load_stage(char* smem, int buf, int tid,
                                           const float* Ab, const float* Bb, int kt) {
    float* sA = (float*)(smem + buf * STAGE_BYTES);
    float* sB = (float*)(smem + buf * STAGE_BYTES + SMA_BYTES);
    const float* Ag = Ab + kt * KT;
    const float* Bg = Bb + (size_t)kt * KT * NPAD;
    #pragma unroll
    for (int p = 0; p < 4; p++) {
        int ci = tid + p * 256;            // 0..1023
        int r = ci >> 3, c = ci & 7;       // A: row 0..127, 16B chunk 0..7
        cp16(smem_u32(sA + r * A_STRIDE + c * 4), Ag + (size_t)r * N_NODES + c * 4);
        int k = ci >> 5, n = ci & 31;      // B: k 0..31, 16B chunk 0..31
        cp16(smem_u32(sB + k * B_STRIDE + n * 4), Bg + k * NPAD + n * 4);
    }
    asm volatile("cp.async.commit_group;" ::: "memory");
}

__global__ __launch_bounds__(256, 1) void gemm_mma(const float* __restrict__ A) {
    extern __shared__ char smem[];
    const int tid  = threadIdx.x;
    const int warp = tid >> 5, lane = tid & 31;
    const int wr = warp >> 2, wc = warp & 3;        // warp grid 2x4
    const int r4 = lane >> 2, c4 = lane & 3;

    const int    row0 = blockIdx.x * 128;
    const size_t k0   = (size_t)blockIdx.y * (N_NODES / KSPLIT);
    const float* Ab   = A   + (size_t)row0 * N_NODES + k0;
    const float* Bb   = g_G + k0 * NPAD;
    const int NT = (N_NODES / KSPLIT) / KT;         // 128 stages

    float acc[4][4][4];
    #pragma unroll
    for (int i = 0; i < 4; i++)
        #pragma unroll
        for (int j = 0; j < 4; j++)
            #pragma unroll
            for (int q = 0; q < 4; q++) acc[i][j][q] = 0.f;

    // prologue: fill the pipe
    #pragma unroll
    for (int s = 0; s < STAGES; s++) load_stage(smem, s, tid, Ab, Bb, s);

    const int abase = (wr * 64 + r4) * A_STRIDE + c4;
    const int bbase = c4 * B_STRIDE + wc * 32 + r4;

    for (int kt = 0; kt < NT; kt++) {
        asm volatile("cp.async.wait_group 2;" ::: "memory");
        __syncthreads();

        const int buf = kt % STAGES;
        const float* As = (const float*)(smem + buf * STAGE_BYTES);
        const float* Bs = (const float*)(smem + buf * STAGE_BYTES + SMA_BYTES);

        #pragma unroll
        for (int k8 = 0; k8 < 4; k8++) {
            uint32_t a[4][4], b[4][2];
            #pragma unroll
            for (int i = 0; i < 4; i++) {
                const float* p = As + abase + i * 16 * A_STRIDE + k8 * 8;
                a[i][0] = f2tf32(p[0]);
                a[i][1] = f2tf32(p[8 * A_STRIDE]);
                a[i][2] = f2tf32(p[4]);
                a[i][3] = f2tf32(p[8 * A_STRIDE + 4]);
            }
            #pragma unroll
            for (int j = 0; j < 4; j++) {               // B pre-rounded at source
                const float* p = Bs + bbase + k8 * 8 * B_STRIDE + j * 8;
                b[j][0] = __float_as_uint(p[0]);
                b[j][1] = __float_as_uint(p[4 * B_STRIDE]);
            }
            #pragma unroll
            for (int i = 0; i < 4; i++)
                #pragma unroll
                for (int j = 0; j < 4; j++)
                    asm volatile(
                        "mma.sync.aligned.m16n8k8.row.col.f32.tf32.tf32.f32 "
                        "{%0,%1,%2,%3}, {%4,%5,%6,%7}, {%8,%9}, {%0,%1,%2,%3};"
                        : "+f"(acc[i][j][0]), "+f"(acc[i][j][1]),
                          "+f"(acc[i][j][2]), "+f"(acc[i][j][3])
                        : "r"(a[i][0]), "r"(a[i][1]), "r"(a[i][2]), "r"(a[i][3]),
                          "r"(b[j][0]), "r"(b[j][1]));
        }
        __syncthreads();

        if (kt + STAGES < NT)
            load_stage(smem, buf, tid, Ab, Bb, kt + STAGES);
        else
            asm volatile("cp.async.commit_group;" ::: "memory");   // empty group keeps count
    }

    // store partials: D row = lane/4 (+8), cols 2*(lane%4)(+1)
    float* P = g_P + ((size_t)blockIdx.y * N_NODES + row0) * NPAD;
    #pragma unroll
    for (int i = 0; i < 4; i++) {
        int r = wr * 64 + i * 16 + r4;
        #pragma unroll
        for (int j = 0; j < 4; j++) {
            int c = wc * 32 + j * 8 + 2 * c4;
            *(float2*)(P + (size_t)r * NPAD + c)       = make_float2(acc[i][j][0], acc[i][j][1]);
            *(float2*)(P + (size_t)(r + 8) * NPAD + c) = make_float2(acc[i][j][2], acc[i][j][3]);
        }
    }
}

// ---------------- 5) epilogue ----------------
__global__ void epi_kernel(const float* __restrict__ b, float* __restrict__ out) {
    int idx = blockIdx.x * 256 + threadIdx.x;   // over N_NODES * NPAD
    int i = idx >> 7, o = idx & 127;
    if (o < F_OUT) {
        const size_t S = (size_t)N_NODES * NPAD;
        float s = g_P[idx] + g_P[idx + S] + g_G[idx];          // split-K + I-term
        float v = fmaf(rsqrtf(g_colsum[i]), s, b[o]);
        out[(size_t)i * F_OUT + o] = fmaxf(v, 0.f);
    }
}

// ---------------- launch ----------------
extern "C" void kernel_launch(void* const* d_in, const int* in_sizes, int n_in,
                              void* d_out, int out_size) {
    const float *A = nullptr, *h0 = nullptr, *W = nullptr, *b = nullptr;
    for (int i = 0; i < n_in; i++) {
        switch (in_sizes[i]) {
            case N_NODES * N_NODES: A  = (const float*)d_in[i]; break;
            case N_NODES * F_IN:    h0 = (const float*)d_in[i]; break;
            case F_OUT * F_IN:      W  = (const float*)d_in[i]; break;
            case F_OUT:             b  = (const float*)d_in[i]; break;
        }
    }
    float* out = (float*)d_out;

    cudaFuncSetAttribute(gemm_mma, cudaFuncAttributeMaxDynamicSharedMemorySize, GEMM_SMEM);

    colsum_part_kernel<<<dim3(N_NODES / 256, RSPLIT), 256>>>(A);
    colsum_fin_kernel<<<N_NODES / 256, 256>>>();
    wt_kernel<<<(F_IN * NPAD + 255) / 256, 256>>>(W);
    g_kernel<<<N_NODES / 32, 256>>>(h0);
    gemm_mma<<<dim3(N_NODES / 128, KSPLIT), 256, GEMM_SMEM>>>(A);
    epi_kernel<<<(N_NODES * NPAD) / 256, 256>>>(b, out);
}

// round 8
// speedup vs baseline: 2.4662x; 1.1361x over previous
#include <cuda_runtime.h>
#include <cuda_bf16.h>
#include <cstdint>

#define N_NODES 8192
#define F_IN    200
#define F_OUT   100
#define NPAD    128
#define KSPLIT  2
#define RSPLIT  16

// ---------------- scratch (no allocations allowed) ----------------
__device__ __align__(16) float g_colsum_part[RSPLIT * N_NODES];
__device__ __align__(16) float g_colsum[N_NODES];
__device__ __align__(16) float g_Wt[F_IN * NPAD];                        // [F_IN][NPAD]
__device__ __align__(16) float g_G [(size_t)N_NODES * NPAD];             // diag(dinv) h0 W^T (fp32)
__device__ __align__(16) __nv_bfloat16 g_Gt[(size_t)NPAD * N_NODES];     // bf16, [n][k]
__device__ __align__(16) float g_P [(size_t)KSPLIT * N_NODES * NPAD];    // split-K partials

// ================= helpers =================
__device__ __forceinline__ uint32_t smem_u32(const void* p) {
    uint32_t a;
    asm("{ .reg .u64 t; cvta.to.shared.u64 t, %1; cvt.u32.u64 %0, t; }" : "=r"(a) : "l"(p));
    return a;
}
__device__ __forceinline__ void cp16(uint32_t s, const void* g) {
    asm volatile("cp.async.cg.shared.global [%0], [%1], 16;" :: "r"(s), "l"(g) : "memory");
}
// pack two fp32 -> bf16x2 (lo = first/lower-k element), round-to-nearest
__device__ __forceinline__ uint32_t pack_bf16x2(float lo, float hi) {
    uint32_t r;
    asm("cvt.rn.bf16x2.f32 %0, %1, %2;" : "=r"(r) : "f"(hi), "f"(lo));
    return r;
}

// ---------------- 1) column sums of A ----------------
__global__ void colsum_part_kernel(const float* __restrict__ A) {
    int j  = blockIdx.x * 256 + threadIdx.x;
    int i0 = blockIdx.y * (N_NODES / RSPLIT);
    const float* p = A + (size_t)i0 * N_NODES + j;
    float s = 0.f;
    #pragma unroll 8
    for (int i = 0; i < N_NODES / RSPLIT; i++) s += p[(size_t)i * N_NODES];
    g_colsum_part[blockIdx.y * N_NODES + j] = s;
}
__global__ void colsum_fin_kernel() {
    int j = blockIdx.x * 256 + threadIdx.x;
    float s = 1.0f;
    #pragma unroll
    for (int p = 0; p < RSPLIT; p++) s += g_colsum_part[p * N_NODES + j];
    g_colsum[j] = s;
}

// ---------------- 2) W -> Wt (zero-padded to NPAD cols) ----------------
__global__ void wt_kernel(const float* __restrict__ W) {
    int idx = blockIdx.x * 256 + threadIdx.x;
    if (idx < F_IN * NPAD) {
        int f = idx >> 7, o = idx & 127;
        g_Wt[idx] = (o < F_OUT) ? W[o * F_IN + f] : 0.f;
    }
}

// ---------------- 3) G = diag(dinv) h0 @ Wt, fp32, 16 rows/CTA (512 CTAs) -------
__global__ __launch_bounds__(256) void g_kernel(const float* __restrict__ h0) {
    __shared__ float h0s[16][8];
    __shared__ float Wts[8][128];
    int t  = threadIdx.x;
    int tx = t & 31, ty = t >> 5;          // ty 0..7
    int row0 = blockIdx.x * 16;
    float acc[2][4] = {};

    for (int kc = 0; kc < F_IN; kc += 8) {
        __syncthreads();
        if (t < 128) {
            int r = t >> 3, kk = t & 7;
            h0s[r][kk] = h0[(size_t)(row0 + r) * F_IN + kc + kk];
        }
        *(float4*)&Wts[ty][tx * 4] = *(const float4*)&g_Wt[(kc + ty) * NPAD + tx * 4];
        __syncthreads();
        #pragma unroll
        for (int k2 = 0; k2 < 8; k2++) {
            float b[4]; *(float4*)b = *(float4*)&Wts[k2][tx * 4];
            #pragma unroll
            for (int i = 0; i < 2; i++) {
                float a = h0s[ty * 2 + i][k2];
                #pragma unroll
                for (int j = 0; j < 4; j++) acc[i][j] = fmaf(a, b[j], acc[i][j]);
            }
        }
    }
    #pragma unroll
    for (int i = 0; i < 2; i++) {
        int row = row0 + ty * 2 + i;
        float dj = rsqrtf(g_colsum[row]);
        float4 v = make_float4(acc[i][0] * dj, acc[i][1] * dj,
                               acc[i][2] * dj, acc[i][3] * dj);
        *(float4*)&g_G[(size_t)row * NPAD + tx * 4] = v;
    }
}

// ---------------- 3b) transpose + bf16: Gt[n][k] = bf16(G[k][n]) ----------------
#define T_STRIDE 132                       // multiple of 4 -> every row base 16B-aligned
__global__ __launch_bounds__(256) void gt_kernel() {
    __shared__ float tile[32][T_STRIDE];   // [j][n]
    int t = threadIdx.x;
    int j0 = blockIdx.x * 32;              // K block of 32
    {   // load 32x128 block of G, coalesced
        int j = t >> 3, c = (t & 7) << 4;  // 16 floats per thread
        #pragma unroll
        for (int q = 0; q < 4; q++)
            *(float4*)&tile[j][c + q * 4] = *(const float4*)&g_G[(size_t)(j0 + j) * NPAD + c + q * 4];
    }
    __syncthreads();
    // write bf16 pairs: thread -> (n, j-pair), lanes sweep j-pairs for coalescing
    int jp = t & 15;                       // j pair 0..15 -> j = 2*jp
    int nb = t >> 4;                       // 0..15
    #pragma unroll
    for (int q = 0; q < 8; q++) {
        int n = nb + q * 16;
        uint32_t v = pack_bf16x2(tile[2 * jp][n], tile[2 * jp + 1][n]);
        *(uint32_t*)&g_Gt[(size_t)n * N_NODES + j0 + 2 * jp] = v;
    }
}

// ---------------- 4) bf16 mma.sync m16n8k16 GEMM: P = A @ G ----------------
// CTA 128x128, KT=32, 3 stages, 8 warps (grid 2x4), warp tile 64x32.
#define KT        32
#define STAGES    3
#define A_STRIDE  40                        // floats; v2-load banks 8*r4+2*c4 conflict-free
#define B_STRIDE  20                        // floats; load banks 20*r4+c4 conflict-free
#define SMA_BYTES (128 * A_STRIDE * 4)      // 20480
#define SMB_BYTES (128 * B_STRIDE * 4)      // 10240
#define STAGE_BYTES (SMA_BYTES + SMB_BYTES)
#define GEMM_SMEM   (STAGES * STAGE_BYTES)  // 92160

__device__ __forceinline__ void load_stage(char* smem, int buf, int tid,
                                           const float* Ab, const __nv_bfloat16* Bb, int kt) {
    float* sA = (float*)(smem + buf * STAGE_BYTES);
    float* sB = (float*)(smem + buf * STAGE_BYTES + SMA_BYTES);
    const float* Ag = Ab + kt * KT;
    const __nv_bfloat16* Bg = Bb + (size_t)kt * KT;
    #pragma unroll
    for (int p = 0; p < 4; p++) {           // A: 1024 x 16B chunks
        int ci = tid + p * 256;
        int r = ci >> 3, c = ci & 7;
        cp16(smem_u32(sA + r * A_STRIDE + c * 4), Ag + (size_t)r * N_NODES + c * 4);
    }
    #pragma unroll
    for (int p = 0; p < 2; p++) {           // B: 512 x 16B chunks, n-major mapping
        int ci = tid + p * 256;
        int n = ci & 127, c = ci >> 7;      // c 0..3: 16B (8 bf16) chunks of the 64B row
        cp16(smem_u32(sB + n * B_STRIDE + c * 4), Bg + (size_t)n * N_NODES + c * 8);
    }
    asm volatile("cp.async.commit_group;" ::: "memory");
}

__global__ __launch_bounds__(256, 1) void gemm_mma(const float* __restrict__ A) {
    extern __shared__ char smem[];
    const int tid  = threadIdx.x;
    const int warp = tid >> 5, lane = tid & 31;
    const int wr = warp >> 2, wc = warp & 3;        // warp grid 2x4
    const int r4 = lane >> 2, c4 = lane & 3;

    const int    row0 = blockIdx.x * 128;
    const size_t k0   = (size_t)blockIdx.y * (N_NODES / KSPLIT);
    const float* Ab   = A + (size_t)row0 * N_NODES + k0;
    const __nv_bfloat16* Bb = g_Gt + k0;
    const int NT = (N_NODES / KSPLIT) / KT;         // 128

    float acc[4][4][4];
    #pragma unroll
    for (int i = 0; i < 4; i++)
        #pragma unroll
        for (int j = 0; j < 4; j++)
            #pragma unroll
            for (int q = 0; q < 4; q++) acc[i][j][q] = 0.f;

    #pragma unroll
    for (int s = 0; s < STAGES; s++) load_stage(smem, s, tid, Ab, Bb, s);

    const int abase = (wr * 64 + r4) * A_STRIDE + 2 * c4;
    const int bbase = (wc * 32 + r4) * B_STRIDE + c4;

    for (int kt = 0; kt < NT; kt++) {
        asm volatile("cp.async.wait_group 2;" ::: "memory");
        __syncthreads();

        const int buf = kt % STAGES;
        const float* As = (const float*)(smem + buf * STAGE_BYTES);
        const float* Bs = (const float*)(smem + buf * STAGE_BYTES + SMA_BYTES);

        #pragma unroll
        for (int k16 = 0; k16 < 2; k16++) {
            uint32_t a[4][4], b[4][2];
            #pragma unroll
            for (int i = 0; i < 4; i++) {
                const float* p = As + abase + i * 16 * A_STRIDE + k16 * 16;
                float2 v0 = *(const float2*)(p);                      // (row, k), (row, k+1)
                float2 v1 = *(const float2*)(p + 8 * A_STRIDE);       // row+8
                float2 v2 = *(const float2*)(p + 8);                  // k+8
                float2 v3 = *(const float2*)(p + 8 * A_STRIDE + 8);
                a[i][0] = pack_bf16x2(v0.x, v0.y);
                a[i][1] = pack_bf16x2(v1.x, v1.y);
                a[i][2] = pack_bf16x2(v2.x, v2.y);
                a[i][3] = pack_bf16x2(v3.x, v3.y);
            }
            #pragma unroll
            for (int j = 0; j < 4; j++) {
                const float* p = Bs + bbase + j * 8 * B_STRIDE + k16 * 8;
                b[j][0] = *(const uint32_t*)(p);        // k pair (2c4, 2c4+1)
                b[j][1] = *(const uint32_t*)(p + 4);    // k pair (+8)
            }
            #pragma unroll
            for (int i = 0; i < 4; i++)
                #pragma unroll
                for (int j = 0; j < 4; j++)
                    asm volatile(
                        "mma.sync.aligned.m16n8k16.row.col.f32.bf16.bf16.f32 "
                        "{%0,%1,%2,%3}, {%4,%5,%6,%7}, {%8,%9}, {%0,%1,%2,%3};"
                        : "+f"(acc[i][j][0]), "+f"(acc[i][j][1]),
                          "+f"(acc[i][j][2]), "+f"(acc[i][j][3])
                        : "r"(a[i][0]), "r"(a[i][1]), "r"(a[i][2]), "r"(a[i][3]),
                          "r"(b[j][0]), "r"(b[j][1]));
        }
        __syncthreads();

        if (kt + STAGES < NT)
            load_stage(smem, buf, tid, Ab, Bb, kt + STAGES);
        else
            asm volatile("cp.async.commit_group;" ::: "memory");
    }

    float* P = g_P + ((size_t)blockIdx.y * N_NODES + row0) * NPAD;
    #pragma unroll
    for (int i = 0; i < 4; i++) {
        int r = wr * 64 + i * 16 + r4;
        #pragma unroll
        for (int j = 0; j < 4; j++) {
            int c = wc * 32 + j * 8 + 2 * c4;
            *(float2*)(P + (size_t)r * NPAD + c)       = make_float2(acc[i][j][0], acc[i][j][1]);
            *(float2*)(P + (size_t)(r + 8) * NPAD + c) = make_float2(acc[i][j][2], acc[i][j][3]);
        }
    }
}

// ---------------- 5) epilogue ----------------
__global__ void epi_kernel(const float* __restrict__ b, float* __restrict__ out) {
    int idx = blockIdx.x * 256 + threadIdx.x;
    int i = idx >> 7, o = idx & 127;
    if (o < F_OUT) {
        const size_t S = (size_t)N_NODES * NPAD;
        float s = g_P[idx] + g_P[idx + S] + g_G[idx];          // split-K + exact I-term
        float v = fmaf(rsqrtf(g_colsum[i]), s, b[o]);
        out[(size_t)i * F_OUT + o] = fmaxf(v, 0.f);
    }
}

// ---------------- launch ----------------
extern "C" void kernel_launch(void* const* d_in, const int* in_sizes, int n_in,
                              void* d_out, int out_size) {
    const float *A = nullptr, *h0 = nullptr, *W = nullptr, *b = nullptr;
    for (int i = 0; i < n_in; i++) {
        switch (in_sizes[i]) {
            case N_NODES * N_NODES: A  = (const float*)d_in[i]; break;
            case N_NODES * F_IN:    h0 = (const float*)d_in[i]; break;
            case F_OUT * F_IN:      W  = (const float*)d_in[i]; break;
            case F_OUT:             b  = (const float*)d_in[i]; break;
        }
    }
    float* out = (float*)d_out;

    cudaFuncSetAttribute(gemm_mma, cudaFuncAttributeMaxDynamicSharedMemorySize, GEMM_SMEM);

    colsum_part_kernel<<<dim3(N_NODES / 256, RSPLIT), 256>>>(A);
    colsum_fin_kernel<<<N_NODES / 256, 256>>>();
    wt_kernel<<<(F_IN * NPAD + 255) / 256, 256>>>(W);
    g_kernel<<<N_NODES / 16, 256>>>(h0);
    gt_kernel<<<N_NODES / 32, 256>>>();
    gemm_mma<<<dim3(N_NODES / 128, KSPLIT), 256, GEMM_SMEM>>>(A);
    epi_kernel<<<(N_NODES * NPAD) / 256, 256>>>(b, out);
}